// round 1
// baseline (speedup 1.0000x reference)
#include <cuda_runtime.h>
#include <cstdint>

#define N_NODES 20000
#define N_EDGES 160000
#define DIM 32          // IN == H == 32
#define EFD 95          // edge feature dim
#define EH 64           // edge hidden
#define NG 64           // graphs
#define ZCOLS 2048      // EH * DIM
#define BN_EPS 1e-5f

// ---------------- scratch (device globals; no runtime allocation) ----------------
__device__ float g_h[(size_t)N_EDGES * EH];        // 41 MB   relu(edge_attr@W1+b1)
__device__ float g_Z[(size_t)N_NODES * ZCOLS];     // 164 MB  X @ perm(W2)
__device__ float g_Zb[N_NODES * DIM];              // X @ reshape(b2)
__device__ float g_agg[N_NODES * DIM];             // scatter-add accumulator
__device__ float g_x1[N_NODES * DIM];              // conv0 output
__device__ float g_pool[NG * DIM];                 // global max pool

// ---------------- zero kernels ----------------
__global__ void k_zero_agg() {
    int i = blockIdx.x * blockDim.x + threadIdx.x;
    if (i < N_NODES * DIM) g_agg[i] = 0.f;
}
__global__ void k_zero_pool() {
    int i = blockIdx.x * blockDim.x + threadIdx.x;
    if (i < NG * DIM) g_pool[i] = 0.f;
}

// ---------------- K1: edge MLP  h = relu(EA @ W1 + b1)  [E,64] ----------------
// block = 256 threads = (16 j-groups of 4) x (16 edges); 16 edges per block.
__global__ void k_edge_mlp(const float* __restrict__ ea,
                           const float* __restrict__ W1,
                           const float* __restrict__ b1) {
    __shared__ float W1s[EFD * EH];     // 24320 B
    __shared__ float eas[16 * EFD];     // 6080 B
    __shared__ float b1s[EH];
    int t = threadIdx.x;
    for (int i = t; i < EFD * EH; i += 256) W1s[i] = W1[i];
    if (t < EH) b1s[t] = b1[t];
    int e0 = blockIdx.x * 16;
    for (int i = t; i < 16 * EFD; i += 256) eas[i] = ea[(size_t)e0 * EFD + i];
    __syncthreads();

    int tx = t & 15, ty = t >> 4;      // tx: 4-wide output group, ty: edge
    int e = e0 + ty;
    float4 acc = make_float4(b1s[tx * 4 + 0], b1s[tx * 4 + 1],
                             b1s[tx * 4 + 2], b1s[tx * 4 + 3]);
    const float* ear = &eas[ty * EFD];
#pragma unroll 5
    for (int k = 0; k < EFD; k++) {
        float a = ear[k];
        float4 w = *(const float4*)&W1s[k * EH + tx * 4];
        acc.x = fmaf(a, w.x, acc.x);
        acc.y = fmaf(a, w.y, acc.y);
        acc.z = fmaf(a, w.z, acc.z);
        acc.w = fmaf(a, w.w, acc.w);
    }
    float4 r = make_float4(fmaxf(acc.x, 0.f), fmaxf(acc.y, 0.f),
                           fmaxf(acc.z, 0.f), fmaxf(acc.w, 0.f));
    *(float4*)&g_h[(size_t)e * EH + tx * 4] = r;
}

// ---------------- K2: Z = X @ B, B[i, k*32+o] = W2[k*1024 + i*32 + o] ----------------
// tile: 64 nodes x 128 cols, 256 threads, each thread 8x4 accumulators.
__global__ void k_zgemm(const float* __restrict__ X, const float* __restrict__ W2) {
    __shared__ float Xs[64 * DIM];      // 8 KB
    __shared__ float Bs[DIM * 128];     // 16 KB
    int t = threadIdx.x;
    int n0 = blockIdx.y * 64;
    int c0 = blockIdx.x * 128;

    for (int i = t; i < 64 * DIM; i += 256) {
        int n = n0 + (i >> 5);
        Xs[i] = (n < N_NODES) ? X[(size_t)n * DIM + (i & 31)] : 0.f;
    }
    for (int i = t; i < DIM * 128; i += 256) {
        int row = i >> 7;               // x-input index i
        int cc = c0 + (i & 127);        // flat Z column = k*32+o
        Bs[i] = W2[(cc >> 5) * 1024 + row * DIM + (cc & 31)];
    }
    __syncthreads();

    int tcol = t & 31, trow = t >> 5;   // trow: 0..7 (8 nodes each)
    float acc[8][4] = {};
#pragma unroll
    for (int i = 0; i < DIM; i++) {
        float4 bv = *(const float4*)&Bs[i * 128 + tcol * 4];
#pragma unroll
        for (int r = 0; r < 8; r++) {
            float a = Xs[(trow * 8 + r) * DIM + i];
            acc[r][0] = fmaf(a, bv.x, acc[r][0]);
            acc[r][1] = fmaf(a, bv.y, acc[r][1]);
            acc[r][2] = fmaf(a, bv.z, acc[r][2]);
            acc[r][3] = fmaf(a, bv.w, acc[r][3]);
        }
    }
#pragma unroll
    for (int r = 0; r < 8; r++) {
        int n = n0 + trow * 8 + r;
        if (n < N_NODES)
            *(float4*)&g_Z[(size_t)n * ZCOLS + c0 + tcol * 4] =
                make_float4(acc[r][0], acc[r][1], acc[r][2], acc[r][3]);
    }
}

// ---------------- K2b: Zb[n,o] = sum_i X[n,i] * b2[i*32+o] ----------------
__global__ void k_zb(const float* __restrict__ X, const float* __restrict__ b2) {
    __shared__ float Bs[DIM * DIM];
    int t = threadIdx.x;
    for (int i = t; i < DIM * DIM; i += 256) Bs[i] = b2[i];
    __syncthreads();
    int n = blockIdx.x * 8 + (t >> 5);
    int o = t & 31;
    const float* xr = X + (size_t)n * DIM;
    float v = 0.f;
#pragma unroll
    for (int i = 0; i < DIM; i++) v = fmaf(xr[i], Bs[i * DIM + o], v);
    g_Zb[n * DIM + o] = v;
}

// ---------------- K3: edge combine + scatter-add ----------------
// warp per edge; lane = output channel o. msg[o] = Zb[src,o] + sum_k h[e,k]*Z[src,k*32+o]
__global__ void k_scatter(const int* __restrict__ src, const int* __restrict__ dst) {
    __shared__ float hsh[8 * EH];       // 8 edges/block
    int t = threadIdx.x;
    size_t hbase = (size_t)blockIdx.x * (8 * EH);
    hsh[t] = g_h[hbase + t];
    hsh[t + 256] = g_h[hbase + t + 256];
    __syncthreads();

    int wid = t >> 5, lane = t & 31;
    int e = blockIdx.x * 8 + wid;
    int s = src[e], d = dst[e];
    const float* zr = g_Z + (size_t)s * ZCOLS + lane;
    const float* hr = &hsh[wid * EH];
    float msg = g_Zb[s * DIM + lane];
#pragma unroll 16
    for (int k = 0; k < EH; k++)
        msg = fmaf(hr[k], __ldg(zr + k * DIM), msg);
    atomicAdd(&g_agg[d * DIM + lane], msg);
}

// ---------------- K4: node update (root GEMM + bias + BN + relu) ----------------
// POOL=false: write to xout.  POOL=true: atomicMax into g_pool (values >= 0).
template <bool POOL>
__global__ void k_node_update(const float* __restrict__ xin,
                              const float* __restrict__ root,
                              const float* __restrict__ bias,
                              const float* __restrict__ bng,
                              const float* __restrict__ bnb,
                              const float* __restrict__ bnrm,
                              const float* __restrict__ bnrv,
                              float* __restrict__ xout,
                              const int* __restrict__ batch) {
    __shared__ float Rs[DIM * DIM];
    int t = threadIdx.x;
    for (int i = t; i < DIM * DIM; i += 256) Rs[i] = root[i];
    __syncthreads();
    int n = blockIdx.x * 8 + (t >> 5);
    int o = t & 31;
    const float* xr = xin + (size_t)n * DIM;
    float v = g_agg[n * DIM + o] + bias[o];
#pragma unroll
    for (int i = 0; i < DIM; i++) v = fmaf(xr[i], Rs[i * DIM + o], v);
    v = (v - bnrm[o]) * rsqrtf(bnrv[o] + BN_EPS) * bng[o] + bnb[o];
    v = fmaxf(v, 0.f);
    if (POOL) {
        int b = batch[n];
        atomicMax((int*)&g_pool[b * DIM + o], __float_as_int(v));
    } else {
        xout[n * DIM + o] = v;
    }
}

// ---------------- K6: head  out = relu(pool @ lin1 + b) @ lin2 + b2 ----------------
__global__ void k_head(const float* __restrict__ l1W, const float* __restrict__ l1b,
                       const float* __restrict__ l2W, const float* __restrict__ l2b,
                       float* __restrict__ out) {
    int g = threadIdx.x;                 // 64 graphs, 64 threads
    const float* pr = &g_pool[g * DIM];
    float tbuf[DIM];
#pragma unroll
    for (int j = 0; j < DIM; j++) {
        float v = l1b[j];
#pragma unroll
        for (int i = 0; i < DIM; i++) v = fmaf(pr[i], l1W[i * DIM + j], v);
        tbuf[j] = fmaxf(v, 0.f);
    }
#pragma unroll
    for (int c = 0; c < 2; c++) {
        float v = l2b[c];
#pragma unroll
        for (int j = 0; j < DIM; j++) v = fmaf(tbuf[j], l2W[j * 2 + c], v);
        out[g * 2 + c] = v;
    }
}

// ---------------- launch ----------------
extern "C" void kernel_launch(void* const* d_in, const int* in_sizes, int n_in,
                              void* d_out, int out_size) {
    const float* x     = (const float*)d_in[0];
    const int*   esrc  = (const int*)d_in[1];
    const int*   edst  = (const int*)d_in[2];
    const float* ea    = (const float*)d_in[3];
    const int*   batch = (const int*)d_in[4];

    const float* c0W1 = (const float*)d_in[5];
    const float* c0b1 = (const float*)d_in[6];
    const float* c0W2 = (const float*)d_in[7];
    const float* c0b2 = (const float*)d_in[8];
    const float* c0rt = (const float*)d_in[9];
    const float* c0bs = (const float*)d_in[10];
    const float* bn0g = (const float*)d_in[11];
    const float* bn0b = (const float*)d_in[12];
    const float* bn0m = (const float*)d_in[13];
    const float* bn0v = (const float*)d_in[14];

    const float* c1W1 = (const float*)d_in[15];
    const float* c1b1 = (const float*)d_in[16];
    const float* c1W2 = (const float*)d_in[17];
    const float* c1b2 = (const float*)d_in[18];
    const float* c1rt = (const float*)d_in[19];
    const float* c1bs = (const float*)d_in[20];
    const float* bn1g = (const float*)d_in[21];
    const float* bn1b = (const float*)d_in[22];
    const float* bn1m = (const float*)d_in[23];
    const float* bn1v = (const float*)d_in[24];

    const float* l1W = (const float*)d_in[25];
    const float* l1b = (const float*)d_in[26];
    const float* l2W = (const float*)d_in[27];
    const float* l2b = (const float*)d_in[28];

    float* out = (float*)d_out;

    void* px1 = nullptr;
    cudaGetSymbolAddress(&px1, g_x1);
    float* x1 = (float*)px1;

    dim3 zg(ZCOLS / 128, (N_NODES + 63) / 64);   // 16 x 313

    // ---- conv0 ----
    k_zero_agg<<<(N_NODES * DIM + 255) / 256, 256>>>();
    k_zero_pool<<<(NG * DIM + 255) / 256, 256>>>();
    k_edge_mlp<<<N_EDGES / 16, 256>>>(ea, c0W1, c0b1);
    k_zgemm<<<zg, 256>>>(x, c0W2);
    k_zb<<<N_NODES / 8, 256>>>(x, c0b2);
    k_scatter<<<N_EDGES / 8, 256>>>(esrc, edst);
    k_node_update<false><<<N_NODES / 8, 256>>>(x, c0rt, c0bs, bn0g, bn0b, bn0m, bn0v,
                                               x1, nullptr);

    // ---- conv1 ----
    k_zero_agg<<<(N_NODES * DIM + 255) / 256, 256>>>();
    k_edge_mlp<<<N_EDGES / 16, 256>>>(ea, c1W1, c1b1);
    k_zgemm<<<zg, 256>>>(x1, c1W2);
    k_zb<<<N_NODES / 8, 256>>>(x1, c1b2);
    k_scatter<<<N_EDGES / 8, 256>>>(esrc, edst);
    k_node_update<true><<<N_NODES / 8, 256>>>(x1, c1rt, c1bs, bn1g, bn1b, bn1m, bn1v,
                                              nullptr, batch);

    // ---- head ----
    k_head<<<1, NG>>>(l1W, l1b, l2W, l2b, out);
}